// round 12
// baseline (speedup 1.0000x reference)
#include <cuda_runtime.h>

// BinaryMaskEdgeSmoothing, R12: shuffle halo in the smem consumer + occ 5.
//
// R11 diagnosis: the per-row stride-16B scalar LDS halos are 4-way bank
// conflicted (8 extra smem phases/row/warp, L1=46%, ALU=38%). Fix: after the
// LDS.128, halos come from neighbor lanes via shuffle; only lanes 0/31 issue
// a predicated single scalar LDS at warp boundaries. Issue pointers are
// incremental (no per-pair IMAD.WIDE chains). launch_bounds(256,5) lifts
// occupancy 47->58% (regs 51 x 1280 thr = 65280 <= 64K regfile).
//
// Rule (verified rel_err = 0.0 since R4; binary inputs make sum9 and
// gsum = 16*blur exact small ints in f32):
//     out = (gsum >= 9) || (gsum == 8 && cen == 1 && sum9 >= 4)
// via: qual = 6*cen + sum9; adj = qual>9.5 ? 0.6 : 0; out = gsum+adj > 8.5.
//
// Pipeline: cp.async pair-granular ring (1 group = 2 rows = 8KB), 4-pair
// 32KB smem ring, wait_group(2) + one syncthreads per 2 rows, edge validity
// peeled into prologue/epilogue.

#define IMG_W   1024
#define IMG_H   1024
#define RPB     16            // output rows per block
#define THREADS 256           // 4 cols per thread
#define NPAIRS  ((RPB + 2) / 2)   // 9 input pairs: rows r0-1 .. r0+RPB
#define ROW_B   (IMG_W * 4)   // bytes per row
#define PAIR_B  (2 * ROW_B)

struct Sums { float t[4], g[4]; };

#define CP_COMMIT() asm volatile("cp.async.commit_group;")
#define CP_WAIT2()  asm volatile("cp.async.wait_group 2;")

__device__ __forceinline__ void cp16(unsigned dst, const float* src) {
    asm volatile("cp.async.cg.shared.global [%0], [%1], 16;" ::
                 "r"(dst), "l"(src));
}

__device__ __forceinline__ Sums make_sums(const float* __restrict__ row,
                                          int x0, int lane,
                                          bool hl, bool hr) {
    float4 v = *reinterpret_cast<const float4*>(row + x0);   // LDS.128
    // Halos from neighbor lanes' registers; warp-boundary lanes load 1 scalar.
    float e0 = __shfl_up_sync(0xFFFFFFFFu,  v.w, 1);
    float e5 = __shfl_down_sync(0xFFFFFFFFu, v.x, 1);
    if (lane == 0)  e0 = hl ? row[x0 - 1] : 0.f;
    if (lane == 31) e5 = hr ? row[x0 + 4] : 0.f;

    Sums s;
    s.t[0] = e0  + v.x + v.y;  s.g[0] = s.t[0] + v.x;
    s.t[1] = v.x + v.y + v.z;  s.g[1] = s.t[1] + v.y;
    s.t[2] = v.y + v.z + v.w;  s.g[2] = s.t[2] + v.z;
    s.t[3] = v.z + v.w + e5;   s.g[3] = s.t[3] + v.w;
    return s;
}

__device__ __forceinline__ Sums zero_sums() {
    Sums s;
    #pragma unroll
    for (int j = 0; j < 4; ++j) { s.t[j] = 0.f; s.g[j] = 0.f; }
    return s;
}

__device__ __forceinline__ float4 compute_row(const Sums& A, const Sums& B,
                                              const Sums& C) {
    float res[4];
    #pragma unroll
    for (int j = 0; j < 4; ++j) {
        float sum9 = A.t[j] + B.t[j] + C.t[j];            // 0..9 exact
        float gsum = fmaf(2.f, B.g[j], A.g[j] + C.g[j]);  // 0..16 exact
        float cen  = B.g[j] - B.t[j];                     // 0 or 1
        float qual = fmaf(6.f, cen, sum9);                // >=10 <=> qualify
        float adj  = (qual > 9.5f) ? 0.6f : 0.f;
        res[j] = (gsum + adj > 8.5f) ? 1.f : 0.f;
    }
    return make_float4(res[0], res[1], res[2], res[3]);
}

__global__ void __launch_bounds__(THREADS, 5)
edge_smooth_kernel(const float* __restrict__ in, float* __restrict__ out) {
    __shared__ float buf[4][2][IMG_W];                    // 4-pair ring, 32KB

    const int img  = blockIdx.y;
    const int r0   = blockIdx.x * RPB;
    const int tid  = threadIdx.x;
    const int x0   = tid * 4;
    const int lane = tid & 31;
    const bool hl  = (x0 > 0);
    const bool hr  = (x0 + 4 < IMG_W);

    const float* gsrc = in + (size_t)img * IMG_H * IMG_W + x0;
    float*       po   = out + ((size_t)img * IMG_H + r0) * IMG_W + x0;
    const float* pmax = gsrc + (size_t)(IMG_H - 1) * IMG_W;   // clamp ptr

    unsigned sb = (unsigned)__cvta_generic_to_shared(&buf[0][0][0]) + tid * 16u;

    // Prologue: pairs 0,1,2 in flight (3 groups). Pair p covers rows
    // r0-1+2p, r0+2p; top row clamps to 0 for the first strip (over-fetched
    // rows are never consumed).
    {
        const float* p0 = gsrc + (size_t)max(r0 - 1, 0) * IMG_W;
        const float* p1 = gsrc + (size_t)r0 * IMG_W;
        cp16(sb,                 p0);
        cp16(sb + ROW_B,         p1); CP_COMMIT();
        cp16(sb + PAIR_B,         p1 + IMG_W);
        cp16(sb + PAIR_B + ROW_B, p1 + 2 * IMG_W); CP_COMMIT();
        cp16(sb + 2 * PAIR_B,         p1 + 3 * IMG_W);
        cp16(sb + 2 * PAIR_B + ROW_B, p1 + 4 * IMG_W); CP_COMMIT();
    }

    // Prime (pair 0): A = row r0-1 (zeros at image top), B = row r0.
    CP_WAIT2(); __syncthreads();
    // Issue pair 3 (rows r0+5, r0+6; interior for all strips since RPB=16
    // and r0 <= 1008 -> r0+6 <= 1014).
    {
        const float* p = gsrc + (size_t)(r0 + 5) * IMG_W;
        cp16(sb + 3 * PAIR_B,         p);
        cp16(sb + 3 * PAIR_B + ROW_B, p + IMG_W);
    }
    CP_COMMIT();
    Sums A = (r0 > 0) ? make_sums(buf[0][0], x0, lane, hl, hr) : zero_sums();
    Sums B = make_sums(buf[0][1], x0, lane, hl, hr);

    // Steady state: consume pairs 1..NPAIRS-2; issue pairs 4..NPAIRS-1.
    const float* pin = gsrc + (size_t)(r0 + 7) * IMG_W;   // pair 4 row0
    for (int i = 1; i <= NPAIRS - 2; ++i) {
        CP_WAIT2(); __syncthreads();
        if (i + 3 < NPAIRS) {
            // Bottom clamp via pointer min (only matters for the last strip).
            const float* q0 = pin     < pmax ? pin         : pmax;
            const float* q1 = pin + IMG_W < pmax ? pin + IMG_W : pmax;
            unsigned dst = sb + (unsigned)((i + 3) & 3) * PAIR_B;
            cp16(dst,         q0);
            cp16(dst + ROW_B, q1);
            pin += 2 * IMG_W;
        }
        CP_COMMIT();

        const int s = i & 3;
        Sums C = make_sums(buf[s][0], x0, lane, hl, hr);
        Sums D = make_sums(buf[s][1], x0, lane, hl, hr);

        *reinterpret_cast<float4*>(po)         = compute_row(A, B, C);
        *reinterpret_cast<float4*>(po + IMG_W) = compute_row(B, C, D);
        po += 2 * IMG_W;

        A = C; B = D;
    }

    // Epilogue (pair NPAIRS-1): bottom row r0+RPB is zeros at image bottom.
    CP_WAIT2(); __syncthreads();
    {
        const int s = (NPAIRS - 1) & 3;
        Sums C = make_sums(buf[s][0], x0, lane, hl, hr);
        Sums D = (r0 + RPB < IMG_H) ? make_sums(buf[s][1], x0, lane, hl, hr)
                                    : zero_sums();
        *reinterpret_cast<float4*>(po)         = compute_row(A, B, C);
        *reinterpret_cast<float4*>(po + IMG_W) = compute_row(B, C, D);
    }
}

extern "C" void kernel_launch(void* const* d_in, const int* in_sizes, int n_in,
                              void* d_out, int out_size) {
    const float* mask = (const float*)d_in[0];   // (B,C,1024,1024) f32
    float*       out  = (float*)d_out;

    int n_imgs = in_sizes[0] / (IMG_H * IMG_W);  // B*C

    dim3 grid(IMG_H / RPB, n_imgs);
    dim3 block(THREADS);
    edge_smooth_kernel<<<grid, block>>>(mask, out);
}